// round 3
// baseline (speedup 1.0000x reference)
#include <cuda_runtime.h>

// B = 16384 samples, D = 2, G = 2500 grid points.
// Y_surf: [B, 2, 2500] f32.  For each b:
//   idx = argmin_g (Ys[b,0,g]-y[b,0])^2 + (Ys[b,1,g]-y[b,1])^2
//   out[b,d] = U_grid[d, idx]
//
// Persistent, fully-resident grid: 512 blocks x 256 threads = 4096 warps,
// all resident at once (regs ~62 -> 4 blocks/SM, capacity 592 >= 512).
// Each warp processes exactly 2 sample-pairs (8192 pairs total) via a fixed
// stride loop -> zero wave-quantization tail.

#define G_CONST 2500
#define G4_CONST 625            // G/4 (2500 % 4 == 0; rows are 16B-aligned)
#define WARPS_PER_BLOCK 8
#define GRID_BLOCKS 512
#define TOTAL_WARPS (GRID_BLOCKS * WARPS_PER_BLOCK)   // 4096

__device__ __forceinline__ void upd(float d2, int g, float& best, int& bidx) {
    // strict '<' keeps FIRST minimum (per-thread indices strictly increase)
    if (d2 < best) { best = d2; bidx = g; }
}

__global__ __launch_bounds__(WARPS_PER_BLOCK * 32)
void lqr_push_kernel3(const float* __restrict__ y,
                      const float* __restrict__ Y_surf,
                      const float* __restrict__ U_grid,
                      float* __restrict__ out,
                      int B)
{
    const int warp = threadIdx.x >> 5;
    const int lane = threadIdx.x & 31;
    const int w    = blockIdx.x * WARPS_PER_BLOCK + warp;

    const int npairs = (B + 1) >> 1;

    for (int p = w; p < npairs; p += TOTAL_WARPS) {
        const int b0 = 2 * p;
        const int b1 = 2 * p + 1;
        const bool has1 = (b1 < B);

        const float y00 = __ldg(&y[2 * b0 + 0]);
        const float y01 = __ldg(&y[2 * b0 + 1]);
        const float y10 = has1 ? __ldg(&y[2 * b1 + 0]) : 0.0f;
        const float y11 = has1 ? __ldg(&y[2 * b1 + 1]) : 0.0f;

        const size_t row0 = (size_t)b0 * (size_t)(2 * G_CONST);
        const size_t row1 = has1 ? (size_t)b1 * (size_t)(2 * G_CONST) : row0;

        const float4* __restrict__ pa = reinterpret_cast<const float4*>(Y_surf + row0);
        const float4* __restrict__ pb = reinterpret_cast<const float4*>(Y_surf + row0 + G_CONST);
        const float4* __restrict__ pc = reinterpret_cast<const float4*>(Y_surf + row1);
        const float4* __restrict__ pd = reinterpret_cast<const float4*>(Y_surf + row1 + G_CONST);

        float best0 = 3.402823466e38f, best1 = 3.402823466e38f;
        int   idx0 = 0, idx1 = 0;

        // 4 independent 16B streaming loads per iteration; unroll 2 -> 8 in flight.
        #pragma unroll 2
        for (int i = lane; i < G4_CONST; i += 32) {
            const float4 a  = __ldcs(pa + i);
            const float4 c  = __ldcs(pc + i);
            const float4 bq = __ldcs(pb + i);
            const float4 d  = __ldcs(pd + i);
            const int g = i << 2;

            float dx, dz;

            dx = a.x - y00; dz = bq.x - y01; upd(dx*dx + dz*dz, g + 0, best0, idx0);
            dx = a.y - y00; dz = bq.y - y01; upd(dx*dx + dz*dz, g + 1, best0, idx0);
            dx = a.z - y00; dz = bq.z - y01; upd(dx*dx + dz*dz, g + 2, best0, idx0);
            dx = a.w - y00; dz = bq.w - y01; upd(dx*dx + dz*dz, g + 3, best0, idx0);

            dx = c.x - y10; dz = d.x - y11; upd(dx*dx + dz*dz, g + 0, best1, idx1);
            dx = c.y - y10; dz = d.y - y11; upd(dx*dx + dz*dz, g + 1, best1, idx1);
            dx = c.z - y10; dz = d.z - y11; upd(dx*dx + dz*dz, g + 2, best1, idx1);
            dx = c.w - y10; dz = d.w - y11; upd(dx*dx + dz*dz, g + 3, best1, idx1);
        }

        // Warp argmin reduction with first-index tie-break, both samples.
        #pragma unroll
        for (int off = 16; off > 0; off >>= 1) {
            const float ov0 = __shfl_xor_sync(0xffffffffu, best0, off);
            const int   oi0 = __shfl_xor_sync(0xffffffffu, idx0,  off);
            if (ov0 < best0 || (ov0 == best0 && oi0 < idx0)) { best0 = ov0; idx0 = oi0; }

            const float ov1 = __shfl_xor_sync(0xffffffffu, best1, off);
            const int   oi1 = __shfl_xor_sync(0xffffffffu, idx1,  off);
            if (ov1 < best1 || (ov1 == best1 && oi1 < idx1)) { best1 = ov1; idx1 = oi1; }
        }

        if (lane == 0) {
            out[2 * b0 + 0] = __ldg(&U_grid[idx0]);
            out[2 * b0 + 1] = __ldg(&U_grid[G_CONST + idx0]);
            if (has1) {
                out[2 * b1 + 0] = __ldg(&U_grid[idx1]);
                out[2 * b1 + 1] = __ldg(&U_grid[G_CONST + idx1]);
            }
        }
    }
}

extern "C" void kernel_launch(void* const* d_in, const int* in_sizes, int n_in,
                              void* d_out, int out_size)
{
    const float* y      = (const float*)d_in[0];   // [B, 2]
    const float* Y_surf = (const float*)d_in[1];   // [B, 2, 2500]
    const float* U_grid = (const float*)d_in[2];   // [2, 2500]
    float* out = (float*)d_out;                    // [B, 2]

    const int B = in_sizes[0] / 2;

    lqr_push_kernel3<<<GRID_BLOCKS, WARPS_PER_BLOCK * 32>>>(y, Y_surf, U_grid, out, B);
}